// round 1
// baseline (speedup 1.0000x reference)
#include <cuda_runtime.h>

#define X 256
#define Y 256
#define Z 192
#define NB 2
#define TX 32
#define TY 16
#define ZCHUNKS 4
#define ZCK (Z / ZCHUNKS)   /* 48 */
#define IX (TX + 4)  /* 36 */
#define IY (TY + 4)  /* 20 */
#define EX (TX + 2)  /* 34 */
#define EY (TY + 2)  /* 18 */
#define NTHREADS 256

__device__ __forceinline__ float finf()  { return __int_as_float(0x7f800000); }
__device__ __forceinline__ float fninf() { return __int_as_float(0xff800000); }

// out = relu(img - dilate3x3x3(erode3x3x3(img))), pool stride 1 pad 1.
// Fused single pass: each block owns a TX x TY x-y tile and marches a z-chunk,
// keeping ring buffers (depth 3 in z) of: img plane (halo 2), 2D-min plane
// (halo 1), and 2D-max plane (interior), with separable 1-D window stages.
__global__ __launch_bounds__(NTHREADS)
void soft_skel_kernel(const float* __restrict__ img, float* __restrict__ out) {
    __shared__ float sImg[3][IY][IX];   // img ring (halo 2)
    __shared__ float sE2 [3][EY][EX];   // 2D erode (min over 3x3 in x,y), halo 1
    __shared__ float sRmn[IY][EX];      // temp: min over x-window
    __shared__ float sEr [EY][EX];      // temp: 3D erode plane (domain-masked)
    __shared__ float sRmx[EY][TX];      // temp: max over x-window of erode
    __shared__ float sD2 [3][TY][TX];   // 2D dilate of erode, interior

    const int tid = threadIdx.x;
    const int bx0 = blockIdx.x * TX;
    const int by0 = blockIdx.y * TY;
    const int bz  = blockIdx.z;
    const int b   = bz / ZCHUNKS;
    const int z0  = (bz % ZCHUNKS) * ZCK;
    const int z1  = z0 + ZCK;

    const float* imgB = img + (size_t)b * Z * Y * X;
    float*       outB = out + (size_t)b * Z * Y * X;

    for (int zi = z0 - 2; zi <= z1 + 1; ++zi) {
        const int sI = (zi + 300) % 3;

        // ---- stage 1: load img plane zi with halo 2; OOB = +inf (min identity)
        {
            const bool zin = (zi >= 0) && (zi < Z);
            const float* p = imgB + (size_t)zi * (Y * X);
            for (int i = tid; i < IY * IX; i += NTHREADS) {
                int iy = i / IX, ix = i - iy * IX;
                int gy = by0 + iy - 2, gx = bx0 + ix - 2;
                float v = finf();
                if (zin && gy >= 0 && gy < Y && gx >= 0 && gx < X)
                    v = p[gy * X + gx];
                sImg[sI][iy][ix] = v;
            }
        }
        __syncthreads();

        // ---- stage 2: min over x-window (3)
        for (int i = tid; i < IY * EX; i += NTHREADS) {
            int iy = i / EX, ex = i - iy * EX;
            float a = sImg[sI][iy][ex];
            a = fminf(a, sImg[sI][iy][ex + 1]);
            a = fminf(a, sImg[sI][iy][ex + 2]);
            sRmn[iy][ex] = a;
        }
        __syncthreads();

        // ---- stage 3: min over y-window -> 2D erode plane for zi
        for (int i = tid; i < EY * EX; i += NTHREADS) {
            int ey = i / EX, ex = i - ey * EX;
            float a = sRmn[ey][ex];
            a = fminf(a, sRmn[ey + 1][ex]);
            a = fminf(a, sRmn[ey + 2][ex]);
            sE2[sI][ey][ex] = a;
        }
        __syncthreads();

        // ---- stages 4-6: 3D erode plane ze = zi-1, then 2D dilate of it
        const int ze = zi - 1;
        if (ze >= z0 - 1) {
            const int s0 = (ze - 1 + 300) % 3;
            const int s1 = (ze     + 300) % 3;
            const int s2 = (ze + 1 + 300) % 3;
            const bool zein = (ze >= 0) && (ze < Z);
            // erode = min over z-window of 2D-min; OUTSIDE domain -> -inf
            // (dilate's max-pool pads with -inf)
            for (int i = tid; i < EY * EX; i += NTHREADS) {
                int ey = i / EX, ex = i - ey * EX;
                int gy = by0 + ey - 1, gx = bx0 + ex - 1;
                float v = fninf();
                if (zein && gy >= 0 && gy < Y && gx >= 0 && gx < X) {
                    float a = sE2[s0][ey][ex];
                    a = fminf(a, sE2[s1][ey][ex]);
                    a = fminf(a, sE2[s2][ey][ex]);
                    v = a;
                }
                sEr[ey][ex] = v;
            }
            __syncthreads();
            // max over x-window
            for (int i = tid; i < EY * TX; i += NTHREADS) {
                int ey = i >> 5, x = i & 31;
                float a = sEr[ey][x];
                a = fmaxf(a, sEr[ey][x + 1]);
                a = fmaxf(a, sEr[ey][x + 2]);
                sRmx[ey][x] = a;
            }
            __syncthreads();
            // max over y-window -> 2D dilate plane for ze
            for (int i = tid; i < TY * TX; i += NTHREADS) {
                int y = i >> 5, x = i & 31;
                float a = sRmx[y][x];
                a = fmaxf(a, sRmx[y + 1][x]);
                a = fmaxf(a, sRmx[y + 2][x]);
                sD2[s1][y][x] = a;
            }
        }

        // ---- stage 7: output plane zo = zi-2
        const int zo = zi - 2;
        if (zo >= z0 && zo < z1) {
            __syncthreads();
            const int d0 = (zo - 1 + 300) % 3;
            const int d1 = (zo     + 300) % 3;
            const int d2 = (zo + 1 + 300) % 3;
            const int sO = d1;
            float* po = outB + (size_t)zo * (Y * X);
            for (int i = tid; i < TY * TX; i += NTHREADS) {
                int y = i >> 5, x = i & 31;
                float o = sD2[d0][y][x];
                o = fmaxf(o, sD2[d1][y][x]);
                o = fmaxf(o, sD2[d2][y][x]);
                float v = sImg[sO][y + 2][x + 2] - o;
                po[(by0 + y) * X + (bx0 + x)] = fmaxf(v, 0.0f);
            }
        }
        __syncthreads();  // protect ring slots before next iteration's writes
    }
}

extern "C" void kernel_launch(void* const* d_in, const int* in_sizes, int n_in,
                              void* d_out, int out_size) {
    (void)in_sizes; (void)n_in; (void)out_size;
    const float* img = (const float*)d_in[0];
    float* out = (float*)d_out;
    dim3 grid(X / TX, Y / TY, NB * ZCHUNKS);
    soft_skel_kernel<<<grid, NTHREADS>>>(img, out);
}

// round 2
// speedup vs baseline: 2.3352x; 2.3352x over previous
#include <cuda_runtime.h>

#define X 256
#define Y 256
#define Z 192
#define YX (X*Y)
#define NB 2
#define TX 64          // output tile width (elements)
#define TY 16          // output tile height
#define CW 34          // float2 columns = (TX+4)/2
#define CH 20          // rows = TY+4 (halo 2 each side)
#define NTH (CW*CH)    // 680 threads
#define ZCHUNKS 4
#define ZCK (Z/ZCHUNKS)

__device__ __forceinline__ float2 fmin2(float2 a, float2 b) {
    return make_float2(fminf(a.x, b.x), fminf(a.y, b.y));
}
__device__ __forceinline__ float2 fmax2(float2 a, float2 b) {
    return make_float2(fmaxf(a.x, b.x), fmaxf(a.y, b.y));
}

// out = relu(img - dilate3x3x3(erode3x3x3(img))), stride 1, pad 1.
// erode = min-pool (pad +inf), dilate = max-pool (pad -inf).
// One thread per (float2-column, y) incl. halo; z marched with register rings:
//   img ring v0..v2 (erode-z), e ring e0..e1+en (dilate-z).
// Per plane: 4 smem stages (ymin, xmin | ymax, xmax) in 2 ping-pong buffers.
__global__ __launch_bounds__(NTH, 2)
void soft_skel_kernel(const float* __restrict__ img, float* __restrict__ out) {
    __shared__ float2 sA[CH * CW];
    __shared__ float2 sB[CH * CW];

    const int tid = threadIdx.x;
    const int cx  = tid % CW;            // float2 column index
    const int iy  = tid / CW;            // row index (with halo)
    const int bx0 = blockIdx.x * TX;
    const int by0 = blockIdx.y * TY;
    const int bz  = blockIdx.z;
    const int b   = bz / ZCHUNKS;
    const int z0  = (bz % ZCHUNKS) * ZCK;
    const int z1  = z0 + ZCK;

    const int gx = bx0 + cx * 2 - 2;     // first element of the pair (even)
    const int gy = by0 + iy - 2;

    // pair is always fully inside or fully outside in x (gx even, X even)
    const bool inImg = (gx >= 0) && (gx < X) && (gy >= 0) && (gy < Y);
    const bool outP  = (iy >= 2) && (iy <= CH - 3) && (cx >= 1) && (cx <= CW - 2);

    // loop-invariant shared offsets (clamped at edges; edge garbage never read)
    const int xl = (cx == 0)      ? 0      : cx - 1;
    const int xr = (cx == CW - 1) ? CW - 1 : cx + 1;
    const int yu = (iy == 0)      ? 0      : iy - 1;
    const int yd = (iy == CH - 1) ? CH - 1 : iy + 1;
    const int offC = iy * CW + cx;
    const int offL = iy * CW + xl;
    const int offR = iy * CW + xr;
    const int offU = yu * CW + cx;
    const int offD = yd * CW + cx;

    const float  PINF = __int_as_float(0x7f800000);
    const float  NINF = __int_as_float(0xff800000);
    const float2 PI2  = make_float2(PINF, PINF);
    const float2 NI2  = make_float2(NINF, NINF);

    const float* imgB = img + (size_t)b * Z * YX + (size_t)gy * X + gx;
    float*       pO   = out + (size_t)b * Z * YX + (size_t)z0 * YX + (size_t)gy * X + gx;

    // img ring: v0 = plane zi-2, v1 = zi-1, v2 = zi (after pipeline fill)
    float2 v0 = PI2, v1 = PI2, v2;
    // erode ring: e0 = e(zi-3), e1 = e(zi-2)
    float2 e0 = NI2, e1 = NI2;

    // preload plane z0-2
    {
        const int zi = z0 - 2;
        v2 = (inImg && zi >= 0 && zi < Z)
               ? *(const float2*)(imgB + (size_t)zi * YX) : PI2;
    }
    const float* pIn = imgB + (size_t)(z0 - 1) * YX;   // next plane to load

    for (int zi = z0 - 2; zi <= z1 + 1; ++zi) {
        // prefetch plane zi+1 (overlaps with this plane's compute)
        float2 vn = PI2;
        const int znext = zi + 1;
        if (inImg && znext >= 0 && znext < Z)
            vn = *(const float2*)pIn;
        pIn += YX;

        // ---- erode-z at plane zc = zi-1 (registers only)
        float2 za = fmin2(v0, fmin2(v1, v2));

        // ---- erode-y (smem)
        sA[offC] = za;
        __syncthreads();
        float2 yb = fmin2(sA[offU], fmin2(za, sA[offD]));
        sB[offC] = yb;
        __syncthreads();

        // ---- erode-x + domain mask for dilate (-inf outside image / z-range)
        {
            float2 L = sB[offL];
            float2 R = sB[offR];
            float ex = fminf(L.y, fminf(yb.x, yb.y));
            float ey = fminf(yb.x, fminf(yb.y, R.x));
            const int zc = zi - 1;
            bool valid = inImg && (zc >= 0) && (zc < Z);
            float2 en = valid ? make_float2(ex, ey) : NI2;

            // ---- dilate-z at plane zo = zi-2 (registers)
            float2 d = fmax2(e0, fmax2(e1, en));
            e0 = e1; e1 = en;

            // ---- dilate-y (smem; sA safe to reuse after the sync above)
            sA[offC] = d;
            __syncthreads();
            float2 m = fmax2(sA[offU], fmax2(d, sA[offD]));
            sB[offC] = m;
            __syncthreads();

            // ---- dilate-x + output: opened at plane zo = zi-2
            if (zi >= z0 + 2) {
                if (outP) {
                    float2 Lm = sB[offL];
                    float2 Rm = sB[offR];
                    float ox = fmaxf(Lm.y, fmaxf(m.x, m.y));
                    float oy = fmaxf(m.x, fmaxf(m.y, Rm.x));
                    float2 r;
                    r.x = fmaxf(v0.x - ox, 0.0f);   // v0 = img at plane zo
                    r.y = fmaxf(v0.y - oy, 0.0f);
                    *(float2*)pO = r;
                }
                pO += YX;
            }
        }

        // shift img ring
        v0 = v1; v1 = v2; v2 = vn;
    }
}

extern "C" void kernel_launch(void* const* d_in, const int* in_sizes, int n_in,
                              void* d_out, int out_size) {
    (void)in_sizes; (void)n_in; (void)out_size;
    const float* img = (const float*)d_in[0];
    float* out = (float*)d_out;
    dim3 grid(X / TX, Y / TY, NB * ZCHUNKS);
    soft_skel_kernel<<<grid, NTH>>>(img, out);
}